// round 3
// baseline (speedup 1.0000x reference)
#include <cuda_runtime.h>
#include <math.h>

#define NB 32
#define HW 1024

#define CKC 169   // x_ul_b channels
#define CQC 166   // ul_b channels
#define COC 160   // ul channels
#define KDIM 16
#define VDIM 80

// ---------------- scratch (static device memory; no allocations) ----------------
__device__ float g_cat [(size_t)NB * CKC * HW];       // x_ul_b [n,169,1024]; ul_b = view +3*HW
__device__ float g_h   [(size_t)NB * CKC * HW];       // GRN hidden
__device__ float g_big [(size_t)NB * 2 * CKC * HW];   // GRN stage-2 raw [2C, hw]
__device__ float g_gout[(size_t)NB * CKC * HW];       // GRN output
__device__ float g_keys[(size_t)NB * KDIM * HW];
__device__ float g_quer[(size_t)NB * KDIM * HW];
__device__ float g_vals[(size_t)NB * VDIM * HW];
__device__ float g_att [(size_t)NB * HW * HW];
__device__ float g_attv[(size_t)NB * VDIM * HW];

__device__ __forceinline__ float eluf(float v) { return v > 0.f ? v : (expf(v) - 1.f); }

__device__ __forceinline__ unsigned f2tf(float v) {
    unsigned r;
    asm("cvt.rna.tf32.f32 %0, %1;" : "=r"(r) : "f"(v));
    return r;
}

__device__ __forceinline__ void mma_tf32(float* d, const unsigned* a, const unsigned* b) {
    asm volatile(
        "mma.sync.aligned.m16n8k8.row.col.f32.tf32.tf32.f32 "
        "{%0,%1,%2,%3}, {%4,%5,%6,%7}, {%8,%9}, {%0,%1,%2,%3};"
        : "+f"(d[0]), "+f"(d[1]), "+f"(d[2]), "+f"(d[3])
        : "r"(a[0]), "r"(a[1]), "r"(a[2]), "r"(a[3]), "r"(b[0]), "r"(b[1]));
}

// ---------------- concat inputs into [n,169,hw] ----------------
__global__ void build_cat_kernel(const float* __restrict__ x, const float* __restrict__ ul,
                                 const float* __restrict__ b, float* __restrict__ cat) {
    long idx = (long)blockIdx.x * blockDim.x + threadIdx.x;
    const long total = (long)NB * CKC * HW;
    if (idx >= total) return;
    int p = (int)(idx % HW);
    int c = (int)((idx / HW) % CKC);
    int n = (int)(idx / ((long)CKC * HW));
    float v;
    if (c < 3)        v = x [((long)n * 3   + c        ) * HW + p];
    else if (c < 163) v = ul[((long)n * 160 + (c - 3)  ) * HW + p];
    else              v = b [((long)n * 6   + (c - 163)) * HW + p];
    cat[idx] = v;
}

// ============ TF32 MMA GEMM: Out = W*concat_elu(X) [+ W2*concat_elu(X2)] + bias[+bias2] ============
// Block tile: 64 out x 128 px. 256 threads = 8 warps, each warp 64(out) x 16(px).
// K chunks of 32 features. A = W (tf32), B = concat_elu(X) (tf32), fp32 accumulate.

#define MG_LOAD_CHUNK(kk)                                                              \
    {                                                                                  \
        const float* Xs; const float* Ws; int Ci; long xs; int fbase;                  \
        if ((kk) < nk1) { Xs = X;  Ws = W;  Ci = Cin;  xs = xStride;  fbase = (kk) * 32; } \
        else            { Xs = X2; Ws = W2; Ci = Cin2; xs = x2Stride; fbase = ((kk) - nk1) * 32; } \
        const int fA = fbase + fw;                                                     \
        _Pragma("unroll")                                                              \
        for (int i = 0; i < 8; ++i) {                                                  \
            const int o = o0 + o8 + i * 8;                                             \
            wreg[i] = (fA < 2 * Ci && o < Cout) ? f2tf(Ws[(long)o * (2 * Ci) + fA]) : 0u; \
        }                                                                              \
        const float* Xn = Xs + (long)n * xs;                                           \
        _Pragma("unroll")                                                              \
        for (int i = 0; i < 16; ++i) {                                                 \
            const int f = fbase + f2 + 2 * i;                                          \
            float v = 0.f;                                                             \
            if (f < 2 * Ci) {                                                          \
                const int c = (f < Ci) ? f : (f - Ci);                                 \
                const float xv = Xn[(long)c * HW + p0 + px];                           \
                v = (f < Ci) ? eluf(xv) : eluf(-xv);                                   \
            }                                                                          \
            xreg[i] = f2tf(v);                                                         \
        }                                                                              \
    }

#define MG_STORE_CHUNK()                                                               \
    {                                                                                  \
        _Pragma("unroll")                                                              \
        for (int i = 0; i < 8; ++i) sA[fw * 68 + o8 + i * 8] = wreg[i];                \
        _Pragma("unroll")                                                              \
        for (int i = 0; i < 16; ++i) sB[(f2 + 2 * i) * 132 + px] = xreg[i];            \
    }

__global__ void __launch_bounds__(256)
mma_gemm_celu(const float* __restrict__ X, long xStride, int Cin,
              const float* __restrict__ W,
              const float* __restrict__ X2, long x2Stride, int Cin2,
              const float* __restrict__ W2,
              const float* __restrict__ bias, const float* __restrict__ bias2,
              int Cout, float* __restrict__ Out, long oStride) {
    __shared__ unsigned sA[32 * 68];    // [feat][out64]  stride 68 (bank-safe)
    __shared__ unsigned sB[32 * 132];   // [feat][px128]  stride 132 (bank-safe)
    const int tid  = threadIdx.x;
    const int warp = tid >> 5;
    const int lane = tid & 31;
    const int n  = blockIdx.y >> 3;
    const int p0 = (blockIdx.y & 7) * 128;
    const int o0 = blockIdx.x * 64;

    // loader indices
    const int fw = tid & 31;     // A: feature
    const int o8 = tid >> 5;     // A: out sub (stride 8)
    const int px = tid & 127;    // B: pixel
    const int f2 = tid >> 7;     // B: feature sub (stride 2)
    // compute indices
    const int px0 = warp * 16;
    const int lq  = lane >> 2;   // 0..7
    const int lr  = lane & 3;    // 0..3

    const int nk1 = (2 * Cin + 31) >> 5;
    const int nk2 = W2 ? ((2 * Cin2 + 31) >> 5) : 0;
    const int nk  = nk1 + nk2;

    unsigned wreg[8], xreg[16];
    float acc[4][2][4];
    #pragma unroll
    for (int m = 0; m < 4; ++m)
        #pragma unroll
        for (int nn = 0; nn < 2; ++nn)
            #pragma unroll
            for (int e = 0; e < 4; ++e) acc[m][nn][e] = 0.f;

    MG_LOAD_CHUNK(0);
    MG_STORE_CHUNK();
    __syncthreads();

    for (int k = 0; k < nk; ++k) {
        if (k + 1 < nk) MG_LOAD_CHUNK(k + 1);
        #pragma unroll
        for (int ks = 0; ks < 4; ++ks) {
            const unsigned* sa0 = &sA[(ks * 8 + lr) * 68];
            const unsigned* sa1 = &sA[(ks * 8 + lr + 4) * 68];
            const unsigned* sb0 = &sB[(ks * 8 + lr) * 132];
            const unsigned* sb1 = &sB[(ks * 8 + lr + 4) * 132];
            unsigned a[4][4], b[2][2];
            #pragma unroll
            for (int m = 0; m < 4; ++m) {
                const int ob = m * 16 + lq;
                a[m][0] = sa0[ob];
                a[m][1] = sa0[ob + 8];
                a[m][2] = sa1[ob];
                a[m][3] = sa1[ob + 8];
            }
            #pragma unroll
            for (int nn = 0; nn < 2; ++nn) {
                const int pb = px0 + nn * 8 + lq;
                b[nn][0] = sb0[pb];
                b[nn][1] = sb1[pb];
            }
            #pragma unroll
            for (int m = 0; m < 4; ++m)
                #pragma unroll
                for (int nn = 0; nn < 2; ++nn)
                    mma_tf32(acc[m][nn], a[m], b[nn]);
        }
        __syncthreads();
        if (k + 1 < nk) { MG_STORE_CHUNK(); __syncthreads(); }
    }

    // epilogue
    #pragma unroll
    for (int m = 0; m < 4; ++m) {
        const int oa = o0 + m * 16 + lq;
        const int ob = oa + 8;
        const float ba = (oa < Cout) ? (bias[oa] + (bias2 ? bias2[oa] : 0.f)) : 0.f;
        const float bb = (ob < Cout) ? (bias[ob] + (bias2 ? bias2[ob] : 0.f)) : 0.f;
        #pragma unroll
        for (int nn = 0; nn < 2; ++nn) {
            const int pp = p0 + px0 + nn * 8 + 2 * lr;
            if (oa < Cout) {
                float2 r = {acc[m][nn][0] + ba, acc[m][nn][1] + ba};
                *reinterpret_cast<float2*>(&Out[(long)n * oStride + (long)oa * HW + pp]) = r;
            }
            if (ob < Cout) {
                float2 r = {acc[m][nn][2] + bb, acc[m][nn][3] + bb};
                *reinterpret_cast<float2*>(&Out[(long)n * oStride + (long)ob * HW + pp]) = r;
            }
        }
    }
}

// ---------------- gate: out = Xres + ga*sigmoid(gb), ga=G[c], gb=G[c+C] ----------------
__global__ void __launch_bounds__(256)
gate_kernel(const float* __restrict__ G, long gStride, int C,
            const float* __restrict__ Xres, long xStride,
            float* __restrict__ Out, long oStride, long total4) {
    long idx = (long)blockIdx.x * blockDim.x + threadIdx.x;
    if (idx >= total4) return;
    const int perImg = C * (HW / 4);
    const int n = (int)(idx / perImg);
    const int r = (int)(idx - (long)n * perImg);
    const int c = r / (HW / 4);
    const int p4 = (r - c * (HW / 4)) * 4;
    const float4 ga = *reinterpret_cast<const float4*>(&G[(long)n * gStride + (long)c * HW + p4]);
    const float4 gb = *reinterpret_cast<const float4*>(&G[(long)n * gStride + (long)(c + C) * HW + p4]);
    const float4 xr = *reinterpret_cast<const float4*>(&Xres[(long)n * xStride + (long)c * HW + p4]);
    float4 o;
    o.x = xr.x + ga.x / (1.f + expf(-gb.x));
    o.y = xr.y + ga.y / (1.f + expf(-gb.y));
    o.z = xr.z + ga.z / (1.f + expf(-gb.z));
    o.w = xr.w + ga.w / (1.f + expf(-gb.w));
    *reinterpret_cast<float4*>(&Out[(long)n * oStride + (long)c * HW + p4]) = o;
}

// ---------------- small projection: Out[n, m0..m0+MT, hw] = W*X + b ----------------
template <int MT>
__global__ void __launch_bounds__(256)
proj_kernel(const float* __restrict__ X, int Cin,
            const float* __restrict__ W, const float* __restrict__ bias,
            float* __restrict__ Out, int M) {
    __shared__ float sW[MT * 176];
    const int n  = blockIdx.y;
    const int m0 = blockIdx.z * MT;
    const int p  = blockIdx.x * 256 + threadIdx.x;
    for (int i = threadIdx.x; i < MT * Cin; i += 256) {
        const int o = i / Cin, c = i - o * Cin;
        sW[o * 176 + c] = W[(long)(m0 + o) * Cin + c];
    }
    __syncthreads();
    const float* Xn = X + (long)n * Cin * HW;
    float acc[MT];
    #pragma unroll
    for (int o = 0; o < MT; ++o) acc[o] = 0.f;
    #pragma unroll 4
    for (int c = 0; c < Cin; ++c) {
        const float v = Xn[(long)c * HW + p];
        #pragma unroll
        for (int o = 0; o < MT; ++o) acc[o] = fmaf(sW[o * 176 + c], v, acc[o]);
    }
    #pragma unroll
    for (int o = 0; o < MT; ++o)
        Out[((long)n * M + m0 + o) * HW + p] = acc[o] + bias[m0 + o];
}

// ---------------- presoftmax: S[n,q,k] = sum_j K[n,j,k]*Q[n,j,q]  (lower tiles only) ----------------
__global__ void qk_kernel(const float* __restrict__ Kt, const float* __restrict__ Qt,
                          float* __restrict__ S) {
    const int n  = blockIdx.z;
    const int q0 = blockIdx.y * 64;
    const int k0 = blockIdx.x * 64;
    if (k0 > q0) return;
    __shared__ float sK[16][64];
    __shared__ float sQ[16][64];
    const float* Kn = Kt + (long)n * KDIM * HW;
    const float* Qn = Qt + (long)n * KDIM * HW;
    const int p  = threadIdx.x & 63;
    const int jr = threadIdx.x >> 6;
    #pragma unroll
    for (int pass = 0; pass < 4; ++pass) {
        const int j = jr + pass * 4;
        sK[j][p] = Kn[(long)j * HW + k0 + p];
        sQ[j][p] = Qn[(long)j * HW + q0 + p];
    }
    __syncthreads();
    const int tx = threadIdx.x & 15, ty = threadIdx.x >> 4;
    float acc[4][4] = {};
    #pragma unroll
    for (int j = 0; j < 16; ++j) {
        const float4 q4 = *reinterpret_cast<const float4*>(&sQ[j][ty * 4]);
        const float4 k4 = *reinterpret_cast<const float4*>(&sK[j][tx * 4]);
        const float qr[4] = {q4.x, q4.y, q4.z, q4.w};
        const float kr[4] = {k4.x, k4.y, k4.z, k4.w};
        #pragma unroll
        for (int i = 0; i < 4; ++i)
            #pragma unroll
            for (int jj = 0; jj < 4; ++jj)
                acc[i][jj] = fmaf(qr[i], kr[jj], acc[i][jj]);
    }
    float* Sn = S + (long)n * HW * HW;
    #pragma unroll
    for (int i = 0; i < 4; ++i) {
        float4 r = {acc[i][0], acc[i][1], acc[i][2], acc[i][3]};
        *reinterpret_cast<float4*>(&Sn[(long)(q0 + ty * 4 + i) * HW + k0 + tx * 4]) = r;
    }
}

// ---------------- causal softmax per row (faithful semantics) ----------------
__global__ void softmax_kernel(float* __restrict__ S) {
    const int q = blockIdx.x;
    const int n = blockIdx.y;
    float* row = S + ((long)n * HW + (long)q) * HW;
    const int tid = threadIdx.x;  // 256
    __shared__ float red[256];

    float vals[4];
    float lmax = 0.f;
    #pragma unroll
    for (int i = 0; i < 4; ++i) {
        const int k = tid + i * 256;
        const float s = (k < q) ? row[k] : 0.f;
        vals[i] = s;
        if (k < q) lmax = fmaxf(lmax, s);
    }
    red[tid] = lmax;
    __syncthreads();
    for (int s2 = 128; s2 > 0; s2 >>= 1) {
        if (tid < s2) red[tid] = fmaxf(red[tid], red[tid + s2]);
        __syncthreads();
    }
    const float m = red[0];
    __syncthreads();

    float e[4];
    float lsum = 0.f;
    #pragma unroll
    for (int i = 0; i < 4; ++i) {
        const int k = tid + i * 256;
        e[i] = (k < q) ? expf(vals[i] - m) : 0.f;
        lsum += e[i];
    }
    red[tid] = lsum;
    __syncthreads();
    for (int s2 = 128; s2 > 0; s2 >>= 1) {
        if (tid < s2) red[tid] += red[tid + s2];
        __syncthreads();
    }
    const float Skept = red[0];
    const float D = Skept + (float)(HW - q) * expf(-m);
    const float inv = 1.f / (Skept + 1e-7f * D);
    const int kmax = (q & ~63) + 64;   // av only consumes k < roundup(q+1, 64)
    #pragma unroll
    for (int i = 0; i < 4; ++i) {
        const int k = tid + i * 256;
        if (k < kmax) row[k] = e[i] * inv;
    }
}

// ---------------- AV: Out[n,v,q] = sum_j Att[n,q,j] * V[n,v,j]  (K causally truncated) ----------------
__global__ void av_kernel(const float* __restrict__ Att, const float* __restrict__ V,
                          float* __restrict__ Out) {
    __shared__ float sV[16][80];
    __shared__ float sW[16][64];
    const int n  = blockIdx.y;
    const int q0 = blockIdx.x * 64;
    const float* An = Att + (long)n * HW * HW;
    const float* Vn = V + (long)n * VDIM * HW;
    const int tx = threadIdx.x & 15, ty = threadIdx.x >> 4;
    float acc[5][4] = {};
    const int jmax = min(HW, q0 + 64);

    for (int j0 = 0; j0 < jmax; j0 += 16) {
        for (int i = threadIdx.x; i < 16 * 80; i += 256) {
            const int v = i >> 4, jj = i & 15;
            sV[jj][v] = Vn[(long)v * HW + j0 + jj];
        }
        for (int i = threadIdx.x; i < 16 * 64; i += 256) {
            const int qq = i >> 4, jj = i & 15;
            sW[jj][qq] = An[(long)(q0 + qq) * HW + j0 + jj];
        }
        __syncthreads();
        #pragma unroll
        for (int jj = 0; jj < 16; ++jj) {
            const float4 w4 = *reinterpret_cast<const float4*>(&sW[jj][tx * 4]);
            const float wv[4] = {w4.x, w4.y, w4.z, w4.w};
            #pragma unroll
            for (int i = 0; i < 5; ++i) {
                const float vv = sV[jj][ty * 5 + i];
                #pragma unroll
                for (int j = 0; j < 4; ++j)
                    acc[i][j] = fmaf(vv, wv[j], acc[i][j]);
            }
        }
        __syncthreads();
    }
    #pragma unroll
    for (int i = 0; i < 5; ++i) {
        float4 r = {acc[i][0], acc[i][1], acc[i][2], acc[i][3]};
        *reinterpret_cast<float4*>(&Out[((long)n * VDIM + ty * 5 + i) * HW + q0 + tx * 4]) = r;
    }
}

// ---------------- launcher ----------------
extern "C" void kernel_launch(void* const* d_in, const int* in_sizes, int n_in,
                              void* d_out, int out_size) {
    (void)in_sizes; (void)n_in; (void)out_size;
    const float* x    = (const float*)d_in[0];
    const float* ul   = (const float*)d_in[1];
    const float* b    = (const float*)d_in[2];
    const float* gkWi = (const float*)d_in[3];
    const float* gkbi = (const float*)d_in[4];
    const float* gkWo = (const float*)d_in[5];
    const float* gkbo = (const float*)d_in[6];
    const float* gqWi = (const float*)d_in[7];
    const float* gqbi = (const float*)d_in[8];
    const float* gqWo = (const float*)d_in[9];
    const float* gqbo = (const float*)d_in[10];
    const float* gvWi = (const float*)d_in[11];
    const float* gvbi = (const float*)d_in[12];
    const float* gvWo = (const float*)d_in[13];
    const float* gvbo = (const float*)d_in[14];
    const float* nkW  = (const float*)d_in[15];
    const float* nkb  = (const float*)d_in[16];
    const float* nqW  = (const float*)d_in[17];
    const float* nqb  = (const float*)d_in[18];
    const float* nvW  = (const float*)d_in[19];
    const float* nvb  = (const float*)d_in[20];
    const float* goWi = (const float*)d_in[21];
    const float* gobi = (const float*)d_in[22];
    const float* goWs = (const float*)d_in[23];
    const float* gobs = (const float*)d_in[24];
    const float* goWo = (const float*)d_in[25];
    const float* gobo = (const float*)d_in[26];
    float* out = (float*)d_out;

    float *p_cat, *p_h, *p_big, *p_gout, *p_keys, *p_quer, *p_vals, *p_att, *p_attv;
    cudaGetSymbolAddress((void**)&p_cat,  g_cat);
    cudaGetSymbolAddress((void**)&p_h,    g_h);
    cudaGetSymbolAddress((void**)&p_big,  g_big);
    cudaGetSymbolAddress((void**)&p_gout, g_gout);
    cudaGetSymbolAddress((void**)&p_keys, g_keys);
    cudaGetSymbolAddress((void**)&p_quer, g_quer);
    cudaGetSymbolAddress((void**)&p_vals, g_vals);
    cudaGetSymbolAddress((void**)&p_att,  g_att);
    cudaGetSymbolAddress((void**)&p_attv, g_attv);

    const long sCat = (long)CKC * HW;
    const long sQ   = (long)CQC * HW;
    const long sO   = (long)COC * HW;
    const long sV   = (long)VDIM * HW;
    const long sBig = (long)2 * CKC * HW;

    {
        const long total = (long)NB * CKC * HW;
        build_cat_kernel<<<(unsigned)((total + 255) / 256), 256>>>(x, ul, b, p_cat);
    }

    const dim3 gridS1(3, NB * 8);   // Cout<=169 -> 3 out-tiles of 64
    const dim3 gridS2K(6, NB * 8);  // Cout=338  -> 6
    const dim3 gridS2Q(6, NB * 8);  // Cout=332  -> 6
    const dim3 gridS2O(5, NB * 8);  // Cout=320  -> 5

    // ---- GRN-K -> keys ----
    mma_gemm_celu<<<gridS1, 256>>>(p_cat, sCat, CKC, gkWi, nullptr, 0, 0, nullptr,
                                   gkbi, nullptr, CKC, p_h, sCat);
    mma_gemm_celu<<<gridS2K, 256>>>(p_h, sCat, CKC, gkWo, nullptr, 0, 0, nullptr,
                                    gkbo, nullptr, 2 * CKC, p_big, sBig);
    {
        const long t4 = (long)NB * CKC * (HW / 4);
        gate_kernel<<<(unsigned)((t4 + 255) / 256), 256>>>(p_big, sBig, CKC, p_cat, sCat, p_gout, sCat, t4);
    }
    proj_kernel<16><<<dim3(4, NB, 1), 256>>>(p_gout, CKC, nkW, nkb, p_keys, KDIM);

    // ---- GRN-Q -> queries (ul_b is a channel-offset view of cat) ----
    mma_gemm_celu<<<gridS1, 256>>>(p_cat + 3 * HW, sCat, CQC, gqWi, nullptr, 0, 0, nullptr,
                                   gqbi, nullptr, CQC, p_h, sQ);
    mma_gemm_celu<<<gridS2Q, 256>>>(p_h, sQ, CQC, gqWo, nullptr, 0, 0, nullptr,
                                    gqbo, nullptr, 2 * CQC, p_big, sBig);
    {
        const long t4 = (long)NB * CQC * (HW / 4);
        gate_kernel<<<(unsigned)((t4 + 255) / 256), 256>>>(p_big, sBig, CQC, p_cat + 3 * HW, sCat, p_gout, sQ, t4);
    }
    proj_kernel<16><<<dim3(4, NB, 1), 256>>>(p_gout, CQC, nqW, nqb, p_quer, KDIM);

    // ---- GRN-V -> values ----
    mma_gemm_celu<<<gridS1, 256>>>(p_cat, sCat, CKC, gvWi, nullptr, 0, 0, nullptr,
                                   gvbi, nullptr, CKC, p_h, sCat);
    mma_gemm_celu<<<gridS2K, 256>>>(p_h, sCat, CKC, gvWo, nullptr, 0, 0, nullptr,
                                    gvbo, nullptr, 2 * CKC, p_big, sBig);
    {
        const long t4 = (long)NB * CKC * (HW / 4);
        gate_kernel<<<(unsigned)((t4 + 255) / 256), 256>>>(p_big, sBig, CKC, p_cat, sCat, p_gout, sCat, t4);
    }
    proj_kernel<16><<<dim3(4, NB, 5), 256>>>(p_gout, CKC, nvW, nvb, p_vals, VDIM);

    // ---- attention ----
    qk_kernel<<<dim3(16, 16, NB), 256>>>(p_keys, p_quer, p_att);
    softmax_kernel<<<dim3(HW, NB), 256>>>(p_att);
    av_kernel<<<dim3(16, NB), 256>>>(p_att, p_vals, p_attv);

    // ---- GRN-O (aux = att_v), dual-input fused stage-1 ----
    mma_gemm_celu<<<gridS1, 256>>>(ul, sO, COC, goWi, p_attv, sV, VDIM, goWs,
                                   gobi, gobs, COC, p_h, sO);
    mma_gemm_celu<<<gridS2O, 256>>>(p_h, sO, COC, goWo, nullptr, 0, 0, nullptr,
                                    gobo, nullptr, 2 * COC, p_big, sBig);
    {
        const long t4 = (long)NB * COC * (HW / 4);
        gate_kernel<<<(unsigned)((t4 + 255) / 256), 256>>>(p_big, sBig, COC, ul, sO, out, sO, t4);
    }
}